// round 2
// baseline (speedup 1.0000x reference)
#include <cuda_runtime.h>
#include <cstdint>

#define N_NODES 50000
#define N_EDGES 800000
#define D_IN    256
#define D_OUT   128

// ---------------- scratch (no allocations allowed) ----------------
__device__ float g_deg [N_NODES];
__device__ float g_dinv[N_NODES];
__device__ float g_h   [(size_t)N_NODES * D_OUT];   // 25.6 MB

// ---------------- 1. degree (self-loop => init 1.0) ----------------
__global__ void k_init_deg(float* deg) {
    int i = blockIdx.x * blockDim.x + threadIdx.x;
    if (i < N_NODES) deg[i] = 1.0f;
}

__global__ void k_count_deg(const int* __restrict__ ei, float* deg) {
    int e = blockIdx.x * blockDim.x + threadIdx.x;
    if (e < N_EDGES) {
        int dst = ei[N_EDGES + e];
        atomicAdd(&deg[dst], 1.0f);
    }
}

__global__ void k_dinv(const float* __restrict__ deg, float* dinv) {
    int i = blockIdx.x * blockDim.x + threadIdx.x;
    if (i < N_NODES) dinv[i] = rsqrtf(deg[i]);
}

// ---------------- 2. GEMM h = x @ W  (fp32, 64x128x32 tiles) ----------------
// block: 256 threads, each computes 8x4 outputs. Full N=128 per block.
__global__ __launch_bounds__(256) void k_gemm(const float* __restrict__ X,
                                              const float* __restrict__ W,
                                              float* __restrict__ H) {
    __shared__ float As[64][32];    // 8 KB
    __shared__ float Bs[32][128];   // 16 KB

    const int tid = threadIdx.x;
    const int tx  = tid & 31;       // 0..31  -> col group (4 cols each)
    const int ty  = tid >> 5;       // 0..7   -> row group (8 rows each)
    const int m0  = blockIdx.x * 64;

    float acc[8][4];
#pragma unroll
    for (int i = 0; i < 8; i++)
#pragma unroll
        for (int j = 0; j < 4; j++) acc[i][j] = 0.0f;

    const float4* X4 = (const float4*)X;     // row stride 64 float4
    const float4* W4 = (const float4*)W;     // row stride 32 float4

    for (int k0 = 0; k0 < D_IN; k0 += 32) {
        // load A tile 64x32 (512 float4, 2 per thread)
#pragma unroll
        for (int p = 0; p < 2; p++) {
            int idx = tid + p * 256;          // 0..511
            int r   = idx >> 3;               // 0..63
            int c4  = idx & 7;                // 0..7
            int gr  = m0 + r;
            float4 v = make_float4(0.f, 0.f, 0.f, 0.f);
            if (gr < N_NODES) v = X4[(size_t)gr * 64 + (k0 >> 2) + c4];
            As[r][c4 * 4 + 0] = v.x;
            As[r][c4 * 4 + 1] = v.y;
            As[r][c4 * 4 + 2] = v.z;
            As[r][c4 * 4 + 3] = v.w;
        }
        // load B tile 32x128 (1024 float4, 4 per thread)
#pragma unroll
        for (int p = 0; p < 4; p++) {
            int idx = tid + p * 256;          // 0..1023
            int r   = idx >> 5;               // 0..31
            int c4  = idx & 31;               // 0..31
            float4 v = W4[(size_t)(k0 + r) * 32 + c4];
            ((float4*)&Bs[r][0])[c4] = v;
        }
        __syncthreads();

#pragma unroll
        for (int k = 0; k < 32; k++) {
            float a[8];
#pragma unroll
            for (int i = 0; i < 8; i++) a[i] = As[ty * 8 + i][k];
            float4 b4 = ((const float4*)&Bs[k][0])[tx];
#pragma unroll
            for (int i = 0; i < 8; i++) {
                acc[i][0] += a[i] * b4.x;
                acc[i][1] += a[i] * b4.y;
                acc[i][2] += a[i] * b4.z;
                acc[i][3] += a[i] * b4.w;
            }
        }
        __syncthreads();
    }

    float4* H4 = (float4*)H;                  // row stride 32 float4
#pragma unroll
    for (int i = 0; i < 8; i++) {
        int gr = m0 + ty * 8 + i;
        if (gr < N_NODES) {
            H4[(size_t)gr * 32 + tx] =
                make_float4(acc[i][0], acc[i][1], acc[i][2], acc[i][3]);
        }
    }
}

// ---------------- 3. out = b + dinv^2 * h (self loop) ----------------
__global__ void k_self(const float* __restrict__ H,
                       const float* __restrict__ dinv,
                       const float* __restrict__ b,
                       float* __restrict__ out) {
    int t = blockIdx.x * blockDim.x + threadIdx.x;   // one per float4
    if (t < N_NODES * 32) {
        int i  = t >> 5;
        int c4 = t & 31;
        float s = dinv[i]; s = s * s;
        float4 h = ((const float4*)H)[t];
        float4 bb = ((const float4*)b)[c4];
        ((float4*)out)[t] = make_float4(h.x * s + bb.x, h.y * s + bb.y,
                                        h.z * s + bb.z, h.w * s + bb.w);
    }
}

// ---------------- 4. edge scatter: one warp per edge ----------------
__global__ __launch_bounds__(256) void k_edge(const int* __restrict__ ei,
                                              const float* __restrict__ H,
                                              const float* __restrict__ dinv,
                                              float* __restrict__ out) {
    int warp = (blockIdx.x * blockDim.x + threadIdx.x) >> 5;
    int lane = threadIdx.x & 31;
    if (warp >= N_EDGES) return;
    int src = ei[warp];
    int dst = ei[N_EDGES + warp];
    float scale = dinv[src] * dinv[dst];
    float4 v = ((const float4*)H)[(size_t)src * 32 + lane];
    float* o = out + (size_t)dst * D_OUT + lane * 4;
    atomicAdd(o + 0, v.x * scale);
    atomicAdd(o + 1, v.y * scale);
    atomicAdd(o + 2, v.z * scale);
    atomicAdd(o + 3, v.w * scale);
}

// ---------------- 5. PReLU in-place ----------------
__global__ void k_prelu(float* __restrict__ out, const float* __restrict__ a) {
    int t = blockIdx.x * blockDim.x + threadIdx.x;
    if (t < N_NODES * D_OUT) {
        float v  = out[t];
        float al = a[t & (D_OUT - 1)];
        out[t] = v > 0.0f ? v : al * v;
    }
}

// ---------------- launch ----------------
extern "C" void kernel_launch(void* const* d_in, const int* in_sizes, int n_in,
                              void* d_out, int out_size) {
    const float* x  = (const float*)d_in[0];
    const int*   ei = (const int*)d_in[1];     // [2, N_EDGES] int32 (JAX x64 disabled)
    const float* W  = (const float*)d_in[2];
    const float* b  = (const float*)d_in[3];
    const float* pa = (const float*)d_in[4];
    float* out = (float*)d_out;

    float* deg;  cudaGetSymbolAddress((void**)&deg,  g_deg);
    float* dinv; cudaGetSymbolAddress((void**)&dinv, g_dinv);
    float* h;    cudaGetSymbolAddress((void**)&h,    g_h);

    k_init_deg<<<(N_NODES + 255) / 256, 256>>>(deg);
    k_count_deg<<<(N_EDGES + 255) / 256, 256>>>(ei, deg);
    k_dinv<<<(N_NODES + 255) / 256, 256>>>(deg, dinv);

    k_gemm<<<(N_NODES + 63) / 64, 256>>>(x, W, h);

    k_self<<<(N_NODES * 32 + 255) / 256, 256>>>(h, dinv, b, out);

    // one warp per edge: 8 warps / 256-thread block
    k_edge<<<(N_EDGES + 7) / 8, 256>>>(ei, h, dinv, out);

    k_prelu<<<(N_NODES * D_OUT + 255) / 256, 256>>>(out, pa);
}